// round 15
// baseline (speedup 1.0000x reference)
#include <cuda_runtime.h>
#include <cuda_fp16.h>
#include <cstdint>

#define NQ 8192
#define MK 8192
#define DD 128
#define WPR 256            // mask words per row
#define BM 64
#define BN 64
#define SPLITS 8
#define CPS (MK / SPLITS)  // 1024 cols per split
#define TT (CPS / BN)      // 16 tiles per CTA
#define THREADS 128
#define NBLK (NQ / BM)     // 128 row blocks

// ---------------- device globals (no allocations allowed) ----------------
__device__ __align__(16) unsigned g_mask[NQ * WPR];                   // 8 MB bitmap
__device__ __align__(256) __half g_qh[NQ * DD];                       // Q * log2(e)/sqrt(d), fp16
__device__ __align__(256) __half g_kh[MK * DD];
__device__ __align__(256) __half g_vt[DD * MK];                       // V transposed [d][m]
__device__ __align__(16) __half g_opart[SPLITS * NQ * DD];            // unnormalized partial O (fp16)
__device__ __align__(16) float g_lpart[SPLITS * NQ];                  // partial softmax sums
__device__ int g_cnt[NBLK];                                           // completion counters (zero-init)

// ---------------- helpers ----------------
__device__ __forceinline__ uint32_t smem_u32(const void* p) {
    uint32_t a;
    asm("{ .reg .u64 t; cvta.to.shared.u64 t, %1; cvt.u32.u64 %0, t; }" : "=r"(a) : "l"(p));
    return a;
}
__device__ __forceinline__ float fexp2(float x) {
    float y; asm("ex2.approx.ftz.f32 %0, %1;" : "=f"(y) : "f"(x)); return y;
}
__device__ __forceinline__ void cp_async16(uint32_t dst, const void* src) {
    asm volatile("cp.async.cg.shared.global [%0], [%1], 16;" :: "r"(dst), "l"(src) : "memory");
}
#define CP_COMMIT()   asm volatile("cp.async.commit_group;" ::: "memory")
#define CP_WAIT_1()   asm volatile("cp.async.wait_group 1;" ::: "memory")

__device__ __forceinline__ void ldsm4(uint32_t& r0, uint32_t& r1, uint32_t& r2, uint32_t& r3,
                                      uint32_t a) {
    asm volatile("ldmatrix.sync.aligned.m8n8.x4.shared.b16 {%0,%1,%2,%3}, [%4];"
                 : "=r"(r0), "=r"(r1), "=r"(r2), "=r"(r3) : "r"(a));
}
__device__ __forceinline__ void mma16816(float* c, uint32_t a0, uint32_t a1, uint32_t a2,
                                         uint32_t a3, uint32_t b0, uint32_t b1) {
    asm volatile("mma.sync.aligned.m16n8k16.row.col.f32.f16.f16.f32 "
                 "{%0,%1,%2,%3}, {%4,%5,%6,%7}, {%8,%9}, {%0,%1,%2,%3};"
                 : "+f"(c[0]), "+f"(c[1]), "+f"(c[2]), "+f"(c[3])
                 : "r"(a0), "r"(a1), "r"(a2), "r"(a3), "r"(b0), "r"(b1));
}

// ---------------- fused prep kernel: clear mask | convert Q,K | transpose V ----------------
__global__ void prep_k(const float* __restrict__ Q, const float* __restrict__ K,
                       const float* __restrict__ V) {
    const int b = blockIdx.x;
    if (b < 2048) {
        ((uint4*)g_mask)[b * 256 + threadIdx.x] = make_uint4(0u, 0u, 0u, 0u);
    } else if (b < 3072) {
        const int i = (b - 2048) * 256 + threadIdx.x;   // float4 index over NQ*DD/4
        const float SC = 0.12753102694653973f;          // log2(e)/sqrt(128)
        float4 q = ((const float4*)Q)[i];
        float4 k = ((const float4*)K)[i];
        __half2* qh2 = (__half2*)g_qh;
        __half2* kh2 = (__half2*)g_kh;
        qh2[i * 2]     = __floats2half2_rn(q.x * SC, q.y * SC);
        qh2[i * 2 + 1] = __floats2half2_rn(q.z * SC, q.w * SC);
        kh2[i * 2]     = __floats2half2_rn(k.x, k.y);
        kh2[i * 2 + 1] = __floats2half2_rn(k.z, k.w);
    } else {
        __shared__ __half tile[32][33];
        const int tb = b - 3072;
        const int bm = tb & 255, bd = tb >> 8;          // 256 x 4 tiles
        const int tx = threadIdx.x & 31, ty = threadIdx.x >> 5;   // 32x8
        const int m0 = bm * 32, d0 = bd * 32;
        #pragma unroll
        for (int i = 0; i < 4; i++) {
            int r = ty + i * 8;
            tile[r][tx] = __float2half_rn(V[(size_t)(m0 + r) * DD + d0 + tx]);
        }
        __syncthreads();
        #pragma unroll
        for (int i = 0; i < 4; i++) {
            int r = ty + i * 8;
            g_vt[(size_t)(d0 + r) * MK + m0 + tx] = tile[tx][r];
        }
    }
}

__global__ void scatter_mask_k(const int* __restrict__ rows, const int* __restrict__ cols, int n) {
    int i = blockIdx.x * blockDim.x + threadIdx.x;
    if (i < n) {
        unsigned r = (unsigned)rows[i], c = (unsigned)cols[i];
        atomicOr(&g_mask[r * WPR + (c >> 5)], 1u << (c & 31u));
    }
}

// ---------------- main attention kernel (warp mma.sync, fp16, 2 CTA/SM) ----------------
// dyn smem (from 1024-aligned base):
//   Qh  [64 rows][256B, chunk-swizzled]   @ 0      (16 KB)
//   buf b (b=0..2) @ 16384 + b*32768:  Kh(16K) Vt(16K)
#define Q_HI 0
#define BUF0 16384
#define BUFSZ 32768
constexpr size_t SMEM_BYTES = 1024 + 16384 + 3 * 32768;   // 115712 -> 2 CTAs/SM

__device__ __forceinline__ void load_kv_tile(uint32_t buf, int c0, int tid) {
    // K: 64 rows x 16 chunks(16B), swizzled chunk = cc ^ (r&7)
    #pragma unroll
    for (int i = 0; i < 8; i++) {
        int w = tid + i * THREADS;
        int r = w >> 4, cc = w & 15;
        cp_async16(buf + r * 256 + ((cc ^ (r & 7)) << 4),
                   g_kh + (size_t)(c0 + r) * DD + cc * 8);
    }
    // Vt: 128 rows(d) x 8 chunks, swizzle cc ^ (d&7)
    #pragma unroll
    for (int i = 0; i < 8; i++) {
        int w = tid + i * THREADS;
        int d = w >> 3, cc = w & 7;
        cp_async16(buf + 16384 + d * 128 + ((cc ^ (d & 7)) << 4),
                   g_vt + (size_t)d * MK + c0 + cc * 8);
    }
}

__global__ __launch_bounds__(THREADS, 2)
void attn_mma_k(float* __restrict__ out) {
    extern __shared__ char smdyn[];
    uint32_t smd = (smem_u32(smdyn) + 1023u) & ~1023u;
    __shared__ int s_old;

    const int tid = threadIdx.x;
    const int wp = tid >> 5;        // 0..3 -> 16 rows each
    const int lane = tid & 31;
    const int g = lane >> 2, tt = lane & 3;
    const int m4 = lane >> 3;       // ldmatrix matrix group 0..3
    const int l7 = lane & 7;

    const int row_blk = blockIdx.x >> 3;        // 128 row blocks
    const int split = blockIdx.x & 7;           // 8 column splits
    const int row0 = row_blk * BM;
    const int cbase = split * CPS;

    // ---- prologue: Q tile (64 rows) + first two KV tiles via cp.async ----
    #pragma unroll
    for (int i = 0; i < 8; i++) {
        int w = tid + i * THREADS;
        int r = w >> 4, cc = w & 15;
        cp_async16(smd + Q_HI + r * 256 + ((cc ^ (r & 7)) << 4),
                   g_qh + (size_t)(row0 + r) * DD + cc * 8);
    }
    load_kv_tile(smd + BUF0, cbase, tid);
    CP_COMMIT();                                     // G0: Q + tile0
    load_kv_tile(smd + BUF0 + BUFSZ, cbase + BN, tid);
    CP_COMMIT();                                     // G1: tile1

    // per-lane ldmatrix address components
    const int a_row = wp * 16 + ((m4 & 1) << 3) + l7;        // Q rows for A frags (<64)
    const uint32_t a_hi = smd + Q_HI + a_row * 256;
    const int a_sw = a_row & 7;
    const int a_ms = m4 >> 1;                                 // chunk select (k-half)
    const int b_rb = ((m4 >> 1) << 3) + l7;                   // B row base within tile
    const int b_sw = b_rb & 7;
    const int b_ms = m4 & 1;

    float oa[16][4];
    #pragma unroll
    for (int i = 0; i < 16; i++)
        #pragma unroll
        for (int j = 0; j < 4; j++) oa[i][j] = 0.f;
    float l0 = 0.f, l1 = 0.f;

    const unsigned* mrow = g_mask + (size_t)(row0 + wp * 16 + g) * WPR + (cbase >> 5);

    // ---- wait for Q + tile0, then hoist Q A-fragments into registers ----
    CP_WAIT_1();
    __syncthreads();
    uint32_t aq[8][4];
    #pragma unroll
    for (int kc = 0; kc < 8; kc++) {
        uint32_t choA = (uint32_t)(((2 * kc + a_ms) ^ a_sw) << 4);
        ldsm4(aq[kc][0], aq[kc][1], aq[kc][2], aq[kc][3], a_hi + choA);
    }

    for (int t = 0; t < TT; t++) {
        const uint32_t buf = smd + BUF0 + (t % 3) * BUFSZ;
        CP_WAIT_1();       // tile t resident (t+1 may still be in flight)
        __syncthreads();   // all warps past PV(t-1) -> buf[(t+2)%3] (== buf[t-1]) free

        if (t + 2 < TT)
            load_kv_tile(smd + BUF0 + ((t + 2) % 3) * BUFSZ, cbase + (t + 2) * BN, tid);
        CP_COMMIT();       // always commit (possibly empty) to keep group window

        // prefetch mask words: LDG latency hides under the S MMAs
        uint2 mw0 = *(const uint2*)(mrow + t * 2);
        uint2 mw1 = *(const uint2*)(mrow + 8 * WPR + t * 2);

        // ---- S = Q*K (fp16 single pass, per warp: 16 x 64; scale pre-folded) ----
        float sc[8][4];
        #pragma unroll
        for (int i = 0; i < 8; i++)
            #pragma unroll
            for (int j = 0; j < 4; j++) sc[i][j] = 0.f;

        #pragma unroll
        for (int kc = 0; kc < 8; kc++) {
            uint32_t choB = (uint32_t)(((2 * kc + b_ms) ^ b_sw) << 4);
            #pragma unroll
            for (int jp = 0; jp < 4; jp++) {
                uint32_t roff = (uint32_t)((jp * 16 + b_rb) * 256) + choB;
                uint32_t bh0, bh1, bh2, bh3;
                ldsm4(bh0, bh1, bh2, bh3, buf + roff);
                mma16816(sc[2 * jp],     aq[kc][0], aq[kc][1], aq[kc][2], aq[kc][3], bh0, bh1);
                mma16816(sc[2 * jp + 1], aq[kc][0], aq[kc][1], aq[kc][2], aq[kc][3], bh2, bh3);
            }
        }

        // ---- mask + exp2 + pack P into fp16 A-fragments ----
        uint32_t ph[4][4];
        #pragma unroll
        for (int j = 0; j < 8; j++) {
            unsigned w0 = (j < 4) ? mw0.x : mw0.y;
            unsigned w1 = (j < 4) ? mw1.x : mw1.y;
            int sh = (j & 3) * 8 + 2 * tt;
            float p00 = ((w0 >> sh) & 1u)       ? 0.f : fexp2(sc[j][0]);
            float p01 = ((w0 >> (sh + 1)) & 1u) ? 0.f : fexp2(sc[j][1]);
            float p10 = ((w1 >> sh) & 1u)       ? 0.f : fexp2(sc[j][2]);
            float p11 = ((w1 >> (sh + 1)) & 1u) ? 0.f : fexp2(sc[j][3]);
            l0 += p00 + p01;
            l1 += p10 + p11;
            __half2 h0 = __floats2half2_rn(p00, p01);
            __half2 h1 = __floats2half2_rn(p10, p11);
            int kc2 = j >> 1, hs = (j & 1) * 2;
            ph[kc2][hs]     = *(uint32_t*)&h0;
            ph[kc2][hs + 1] = *(uint32_t*)&h1;
        }

        // ---- O += P*V  (per warp: 16 x 128) ----
        const uint32_t vh = buf + 16384;
        #pragma unroll
        for (int kc2 = 0; kc2 < 4; kc2++) {
            uint32_t cho = (uint32_t)(((2 * kc2 + b_ms) ^ b_sw) << 4);
            #pragma unroll
            for (int p = 0; p < 8; p++) {
                uint32_t roff = (uint32_t)((p * 16 + b_rb) * 128) + cho;
                uint32_t vh0, vh1, vh2, vh3;
                ldsm4(vh0, vh1, vh2, vh3, vh + roff);
                mma16816(oa[2 * p],     ph[kc2][0], ph[kc2][1], ph[kc2][2], ph[kc2][3], vh0, vh1);
                mma16816(oa[2 * p + 1], ph[kc2][0], ph[kc2][1], ph[kc2][2], ph[kc2][3], vh2, vh3);
            }
        }
    }

    // ---- reduce l across the 4 lanes of each row group ----
    #pragma unroll
    for (int off = 1; off < 4; off <<= 1) {
        l0 += __shfl_xor_sync(0xffffffffu, l0, off);
        l1 += __shfl_xor_sync(0xffffffffu, l1, off);
    }

    // ---- store unnormalized partial O (fp16) + l ----
    {
        const int r0g = row0 + wp * 16 + g;
        __half* op0 = g_opart + ((size_t)split * NQ + r0g) * DD;
        __half* op1 = op0 + 8 * DD;
        #pragma unroll
        for (int dn = 0; dn < 16; dn++) {
            *(__half2*)(op0 + dn * 8 + 2 * tt) = __floats2half2_rn(oa[dn][0], oa[dn][1]);
            *(__half2*)(op1 + dn * 8 + 2 * tt) = __floats2half2_rn(oa[dn][2], oa[dn][3]);
        }
        if (tt == 0) {
            g_lpart[(size_t)split * NQ + r0g] = l0;
            g_lpart[(size_t)split * NQ + r0g + 8] = l1;
        }
    }

    // ---- fused combine: last split-CTA of this row block normalizes + writes out ----
    __threadfence();                      // make this CTA's partials globally visible
    __syncthreads();
    if (tid == 0)
        s_old = atomicAdd(&g_cnt[row_blk], 1);
    __syncthreads();
    if (s_old == SPLITS - 1) {
        // all 8 partials for row block are visible (each fenced before its arrive)
        for (int idx = tid; idx < BM * (DD / 8); idx += THREADS) {
            int r = idx >> 4;                       // row within block
            int c8 = idx & 15;                      // 8-half chunk within row
            int grow = row0 + r;
            float lsum = 0.f;
            #pragma unroll
            for (int s = 0; s < SPLITS; s++) lsum += g_lpart[s * NQ + grow];
            float inv = 1.f / lsum;
            float acc[8];
            #pragma unroll
            for (int j = 0; j < 8; j++) acc[j] = 0.f;
            #pragma unroll
            for (int s = 0; s < SPLITS; s++) {
                uint4 v = *(const uint4*)(g_opart + ((size_t)s * NQ + grow) * DD + c8 * 8);
                float2 a0 = __half22float2(*(__half2*)&v.x);
                float2 a1 = __half22float2(*(__half2*)&v.y);
                float2 a2 = __half22float2(*(__half2*)&v.z);
                float2 a3 = __half22float2(*(__half2*)&v.w);
                acc[0] += a0.x; acc[1] += a0.y; acc[2] += a1.x; acc[3] += a1.y;
                acc[4] += a2.x; acc[5] += a2.y; acc[6] += a3.x; acc[7] += a3.y;
            }
            float4* o = (float4*)(out + (size_t)grow * DD + c8 * 8);
            o[0] = make_float4(acc[0] * inv, acc[1] * inv, acc[2] * inv, acc[3] * inv);
            o[1] = make_float4(acc[4] * inv, acc[5] * inv, acc[6] * inv, acc[7] * inv);
        }
        __syncthreads();
        if (tid == 0) g_cnt[row_blk] = 0;   // self-clean for next graph replay
    }
}

// ---------------- launcher ----------------
extern "C" void kernel_launch(void* const* d_in, const int* in_sizes, int n_in,
                              void* d_out, int out_size) {
    const float* Q  = (const float*)d_in[0];
    const float* K  = (const float*)d_in[1];
    const float* V  = (const float*)d_in[2];
    const int*   mr = (const int*)d_in[3];
    const int*   mc = (const int*)d_in[4];
    const int nmask = in_sizes[3];
    float* Out = (float*)d_out;

    cudaFuncSetAttribute(attn_mma_k, cudaFuncAttributeMaxDynamicSharedMemorySize,
                         (int)SMEM_BYTES);

    prep_k<<<4096, 256>>>(Q, K, V);
    scatter_mask_k<<<(nmask + 255) / 256, 256>>>(mr, mc, nmask);
    attn_mma_k<<<NBLK * SPLITS, THREADS, SMEM_BYTES>>>(Out);
}

// round 16
// speedup vs baseline: 1.3473x; 1.3473x over previous
#include <cuda_runtime.h>
#include <cuda_fp16.h>
#include <cstdint>

#define NQ 8192
#define MK 8192
#define DD 128
#define WPR 256            // mask words per row
#define BM 64
#define BN 64
#define SPLITS 8
#define CPS (MK / SPLITS)  // 1024 cols per split
#define TT (CPS / BN)      // 16 tiles per CTA
#define THREADS 128

// ---------------- device globals (no allocations allowed) ----------------
// g_mask invariant: all-zero at kernel_launch entry (zero at module load;
// attn_mma_k zeroes its own region after consuming it each run).
__device__ __align__(16) unsigned g_mask[NQ * WPR];                   // 8 MB bitmap
__device__ __align__(256) __half g_qh[NQ * DD];                       // Q * log2(e)/sqrt(d), fp16
__device__ __align__(256) __half g_kh[MK * DD];
__device__ __align__(256) __half g_vt[DD * MK];                       // V transposed [d][m]
__device__ __align__(16) __half g_opart[SPLITS * NQ * DD];            // unnormalized partial O (fp16)
__device__ __align__(16) float g_lpart[SPLITS * NQ];                  // partial softmax sums

// ---------------- helpers ----------------
__device__ __forceinline__ uint32_t smem_u32(const void* p) {
    uint32_t a;
    asm("{ .reg .u64 t; cvta.to.shared.u64 t, %1; cvt.u32.u64 %0, t; }" : "=r"(a) : "l"(p));
    return a;
}
__device__ __forceinline__ float fexp2(float x) {
    float y; asm("ex2.approx.ftz.f32 %0, %1;" : "=f"(y) : "f"(x)); return y;
}
__device__ __forceinline__ void cp_async16(uint32_t dst, const void* src) {
    asm volatile("cp.async.cg.shared.global [%0], [%1], 16;" :: "r"(dst), "l"(src) : "memory");
}
#define CP_COMMIT()   asm volatile("cp.async.commit_group;" ::: "memory")
#define CP_WAIT_1()   asm volatile("cp.async.wait_group 1;" ::: "memory")

__device__ __forceinline__ void ldsm4(uint32_t& r0, uint32_t& r1, uint32_t& r2, uint32_t& r3,
                                      uint32_t a) {
    asm volatile("ldmatrix.sync.aligned.m8n8.x4.shared.b16 {%0,%1,%2,%3}, [%4];"
                 : "=r"(r0), "=r"(r1), "=r"(r2), "=r"(r3) : "r"(a));
}
__device__ __forceinline__ void mma16816(float* c, uint32_t a0, uint32_t a1, uint32_t a2,
                                         uint32_t a3, uint32_t b0, uint32_t b1) {
    asm volatile("mma.sync.aligned.m16n8k16.row.col.f32.f16.f16.f32 "
                 "{%0,%1,%2,%3}, {%4,%5,%6,%7}, {%8,%9}, {%0,%1,%2,%3};"
                 : "+f"(c[0]), "+f"(c[1]), "+f"(c[2]), "+f"(c[3])
                 : "r"(a0), "r"(a1), "r"(a2), "r"(a3), "r"(b0), "r"(b1));
}

// ---------------- fused prep kernel: convert Q,K | transpose V (no mask clear) ----------------
__global__ void prep_k(const float* __restrict__ Q, const float* __restrict__ K,
                       const float* __restrict__ V) {
    const int b = blockIdx.x;
    if (b < 1024) {
        const int i = b * 256 + threadIdx.x;            // float4 index over NQ*DD/4
        const float SC = 0.12753102694653973f;          // log2(e)/sqrt(128)
        float4 q = ((const float4*)Q)[i];
        float4 k = ((const float4*)K)[i];
        __half2* qh2 = (__half2*)g_qh;
        __half2* kh2 = (__half2*)g_kh;
        qh2[i * 2]     = __floats2half2_rn(q.x * SC, q.y * SC);
        qh2[i * 2 + 1] = __floats2half2_rn(q.z * SC, q.w * SC);
        kh2[i * 2]     = __floats2half2_rn(k.x, k.y);
        kh2[i * 2 + 1] = __floats2half2_rn(k.z, k.w);
    } else {
        __shared__ __half tile[32][33];
        const int tb = b - 1024;
        const int bm = tb & 255, bd = tb >> 8;          // 256 x 4 tiles
        const int tx = threadIdx.x & 31, ty = threadIdx.x >> 5;   // 32x8
        const int m0 = bm * 32, d0 = bd * 32;
        #pragma unroll
        for (int i = 0; i < 4; i++) {
            int r = ty + i * 8;
            tile[r][tx] = __float2half_rn(V[(size_t)(m0 + r) * DD + d0 + tx]);
        }
        __syncthreads();
        #pragma unroll
        for (int i = 0; i < 4; i++) {
            int r = ty + i * 8;
            g_vt[(size_t)(d0 + r) * MK + m0 + tx] = tile[tx][r];
        }
    }
}

__global__ void scatter_mask_k(const int* __restrict__ rows, const int* __restrict__ cols, int n) {
    int i = blockIdx.x * blockDim.x + threadIdx.x;
    if (i < n) {
        unsigned r = (unsigned)rows[i], c = (unsigned)cols[i];
        atomicOr(&g_mask[r * WPR + (c >> 5)], 1u << (c & 31u));
    }
}

// each thread: one 16-byte chunk (8 halves) per split
__global__ void combine_k(float* __restrict__ out) {
    int i = blockIdx.x * blockDim.x + threadIdx.x;  // 8-half chunk index
    if (i >= NQ * DD / 8) return;
    int row = i >> 4;                               // 16 chunks per row
    float lsum = 0.f;
    #pragma unroll
    for (int s = 0; s < SPLITS; s++) lsum += g_lpart[s * NQ + row];
    float inv = 1.f / lsum;

    float acc[8];
    #pragma unroll
    for (int j = 0; j < 8; j++) acc[j] = 0.f;
    #pragma unroll
    for (int s = 0; s < SPLITS; s++) {
        uint4 v = ((const uint4*)(g_opart + (size_t)s * NQ * DD))[i];
        float2 a0 = __half22float2(*(__half2*)&v.x);
        float2 a1 = __half22float2(*(__half2*)&v.y);
        float2 a2 = __half22float2(*(__half2*)&v.z);
        float2 a3 = __half22float2(*(__half2*)&v.w);
        acc[0] += a0.x; acc[1] += a0.y; acc[2] += a1.x; acc[3] += a1.y;
        acc[4] += a2.x; acc[5] += a2.y; acc[6] += a3.x; acc[7] += a3.y;
    }
    float4* o = (float4*)(out + (size_t)i * 8);
    o[0] = make_float4(acc[0] * inv, acc[1] * inv, acc[2] * inv, acc[3] * inv);
    o[1] = make_float4(acc[4] * inv, acc[5] * inv, acc[6] * inv, acc[7] * inv);
}

// ---------------- main attention kernel (warp mma.sync, fp16, 2 CTA/SM) ----------------
// dyn smem (from 1024-aligned base):
//   Qh  [64 rows][256B, chunk-swizzled]   @ 0      (16 KB)
//   buf b (b=0..2) @ 16384 + b*32768:  Kh(16K) Vt(16K)
#define Q_HI 0
#define BUF0 16384
#define BUFSZ 32768
constexpr size_t SMEM_BYTES = 1024 + 16384 + 3 * 32768;   // 115712 -> 2 CTAs/SM

__device__ __forceinline__ void load_kv_tile(uint32_t buf, int c0, int tid) {
    // K: 64 rows x 16 chunks(16B), swizzled chunk = cc ^ (r&7)
    #pragma unroll
    for (int i = 0; i < 8; i++) {
        int w = tid + i * THREADS;
        int r = w >> 4, cc = w & 15;
        cp_async16(buf + r * 256 + ((cc ^ (r & 7)) << 4),
                   g_kh + (size_t)(c0 + r) * DD + cc * 8);
    }
    // Vt: 128 rows(d) x 8 chunks, swizzle cc ^ (d&7)
    #pragma unroll
    for (int i = 0; i < 8; i++) {
        int w = tid + i * THREADS;
        int d = w >> 3, cc = w & 7;
        cp_async16(buf + 16384 + d * 128 + ((cc ^ (d & 7)) << 4),
                   g_vt + (size_t)d * MK + c0 + cc * 8);
    }
}

__global__ __launch_bounds__(THREADS, 2)
void attn_mma_k() {
    extern __shared__ char smdyn[];
    uint32_t smd = (smem_u32(smdyn) + 1023u) & ~1023u;

    const int tid = threadIdx.x;
    const int wp = tid >> 5;        // 0..3 -> 16 rows each
    const int lane = tid & 31;
    const int g = lane >> 2, tt = lane & 3;
    const int m4 = lane >> 3;       // ldmatrix matrix group 0..3
    const int l7 = lane & 7;

    const int row_blk = blockIdx.x >> 3;        // 128 row blocks
    const int split = blockIdx.x & 7;           // 8 column splits
    const int row0 = row_blk * BM;
    const int cbase = split * CPS;

    // ---- prologue: Q tile (64 rows) + first two KV tiles via cp.async ----
    #pragma unroll
    for (int i = 0; i < 8; i++) {
        int w = tid + i * THREADS;
        int r = w >> 4, cc = w & 15;
        cp_async16(smd + Q_HI + r * 256 + ((cc ^ (r & 7)) << 4),
                   g_qh + (size_t)(row0 + r) * DD + cc * 8);
    }
    load_kv_tile(smd + BUF0, cbase, tid);
    CP_COMMIT();                                     // G0: Q + tile0
    load_kv_tile(smd + BUF0 + BUFSZ, cbase + BN, tid);
    CP_COMMIT();                                     // G1: tile1

    // per-lane ldmatrix address components
    const int a_row = wp * 16 + ((m4 & 1) << 3) + l7;        // Q rows for A frags (<64)
    const uint32_t a_hi = smd + Q_HI + a_row * 256;
    const int a_sw = a_row & 7;
    const int a_ms = m4 >> 1;                                 // chunk select (k-half)
    const int b_rb = ((m4 >> 1) << 3) + l7;                   // B row base within tile
    const int b_sw = b_rb & 7;
    const int b_ms = m4 & 1;

    float oa[16][4];
    #pragma unroll
    for (int i = 0; i < 16; i++)
        #pragma unroll
        for (int j = 0; j < 4; j++) oa[i][j] = 0.f;
    float l0 = 0.f, l1 = 0.f;

    const unsigned* mrow = g_mask + (size_t)(row0 + wp * 16 + g) * WPR + (cbase >> 5);

    // ---- wait for Q + tile0, then hoist Q A-fragments into registers ----
    CP_WAIT_1();
    __syncthreads();
    uint32_t aq[8][4];
    #pragma unroll
    for (int kc = 0; kc < 8; kc++) {
        uint32_t choA = (uint32_t)(((2 * kc + a_ms) ^ a_sw) << 4);
        ldsm4(aq[kc][0], aq[kc][1], aq[kc][2], aq[kc][3], a_hi + choA);
    }

    for (int t = 0; t < TT; t++) {
        const uint32_t buf = smd + BUF0 + (t % 3) * BUFSZ;
        CP_WAIT_1();       // tile t resident (t+1 may still be in flight)
        __syncthreads();   // all warps past PV(t-1) -> buf[(t+2)%3] (== buf[t-1]) free

        if (t + 2 < TT)
            load_kv_tile(smd + BUF0 + ((t + 2) % 3) * BUFSZ, cbase + (t + 2) * BN, tid);
        CP_COMMIT();       // always commit (possibly empty) to keep group window

        // prefetch mask words: LDG latency hides under the S MMAs
        uint2 mw0 = *(const uint2*)(mrow + t * 2);
        uint2 mw1 = *(const uint2*)(mrow + 8 * WPR + t * 2);

        // ---- S = Q*K (fp16 single pass, per warp: 16 x 64; scale pre-folded) ----
        float sc[8][4];
        #pragma unroll
        for (int i = 0; i < 8; i++)
            #pragma unroll
            for (int j = 0; j < 4; j++) sc[i][j] = 0.f;

        #pragma unroll
        for (int kc = 0; kc < 8; kc++) {
            uint32_t choB = (uint32_t)(((2 * kc + b_ms) ^ b_sw) << 4);
            #pragma unroll
            for (int jp = 0; jp < 4; jp++) {
                uint32_t roff = (uint32_t)((jp * 16 + b_rb) * 256) + choB;
                uint32_t bh0, bh1, bh2, bh3;
                ldsm4(bh0, bh1, bh2, bh3, buf + roff);
                mma16816(sc[2 * jp],     aq[kc][0], aq[kc][1], aq[kc][2], aq[kc][3], bh0, bh1);
                mma16816(sc[2 * jp + 1], aq[kc][0], aq[kc][1], aq[kc][2], aq[kc][3], bh2, bh3);
            }
        }

        // ---- mask + exp2 + pack P into fp16 A-fragments ----
        uint32_t ph[4][4];
        #pragma unroll
        for (int j = 0; j < 8; j++) {
            unsigned w0 = (j < 4) ? mw0.x : mw0.y;
            unsigned w1 = (j < 4) ? mw1.x : mw1.y;
            int sh = (j & 3) * 8 + 2 * tt;
            float p00 = ((w0 >> sh) & 1u)       ? 0.f : fexp2(sc[j][0]);
            float p01 = ((w0 >> (sh + 1)) & 1u) ? 0.f : fexp2(sc[j][1]);
            float p10 = ((w1 >> sh) & 1u)       ? 0.f : fexp2(sc[j][2]);
            float p11 = ((w1 >> (sh + 1)) & 1u) ? 0.f : fexp2(sc[j][3]);
            l0 += p00 + p01;
            l1 += p10 + p11;
            __half2 h0 = __floats2half2_rn(p00, p01);
            __half2 h1 = __floats2half2_rn(p10, p11);
            int kc2 = j >> 1, hs = (j & 1) * 2;
            ph[kc2][hs]     = *(uint32_t*)&h0;
            ph[kc2][hs + 1] = *(uint32_t*)&h1;
        }

        // ---- O += P*V  (per warp: 16 x 128) ----
        const uint32_t vh = buf + 16384;
        #pragma unroll
        for (int kc2 = 0; kc2 < 4; kc2++) {
            uint32_t cho = (uint32_t)(((2 * kc2 + b_ms) ^ b_sw) << 4);
            #pragma unroll
            for (int p = 0; p < 8; p++) {
                uint32_t roff = (uint32_t)((p * 16 + b_rb) * 128) + cho;
                uint32_t vh0, vh1, vh2, vh3;
                ldsm4(vh0, vh1, vh2, vh3, vh + roff);
                mma16816(oa[2 * p],     ph[kc2][0], ph[kc2][1], ph[kc2][2], ph[kc2][3], vh0, vh1);
                mma16816(oa[2 * p + 1], ph[kc2][0], ph[kc2][1], ph[kc2][2], ph[kc2][3], vh2, vh3);
            }
        }
    }

    // ---- self-clean this CTA's mask region (all reads above are complete) ----
    // region: rows [row0, row0+64) x words [cbase/32, cbase/32+32) -> 64 x 8 uint4
    __syncthreads();   // every warp finished its mask loads for all t
    {
        const int wbase = cbase >> 5;
        #pragma unroll
        for (int i = 0; i < 4; i++) {
            int idx = tid + i * THREADS;           // 0..511
            int r = idx >> 3, c4 = idx & 7;
            *(uint4*)(g_mask + (size_t)(row0 + r) * WPR + wbase + c4 * 4) =
                make_uint4(0u, 0u, 0u, 0u);
        }
    }

    // ---- reduce l across the 4 lanes of each row group ----
    #pragma unroll
    for (int off = 1; off < 4; off <<= 1) {
        l0 += __shfl_xor_sync(0xffffffffu, l0, off);
        l1 += __shfl_xor_sync(0xffffffffu, l1, off);
    }

    // ---- store unnormalized partial O (fp16) + l ----
    {
        const int r0g = row0 + wp * 16 + g;
        __half* op0 = g_opart + ((size_t)split * NQ + r0g) * DD;
        __half* op1 = op0 + 8 * DD;
        #pragma unroll
        for (int dn = 0; dn < 16; dn++) {
            *(__half2*)(op0 + dn * 8 + 2 * tt) = __floats2half2_rn(oa[dn][0], oa[dn][1]);
            *(__half2*)(op1 + dn * 8 + 2 * tt) = __floats2half2_rn(oa[dn][2], oa[dn][3]);
        }
        if (tt == 0) {
            g_lpart[(size_t)split * NQ + r0g] = l0;
            g_lpart[(size_t)split * NQ + r0g + 8] = l1;
        }
    }
}

// ---------------- launcher ----------------
extern "C" void kernel_launch(void* const* d_in, const int* in_sizes, int n_in,
                              void* d_out, int out_size) {
    const float* Q  = (const float*)d_in[0];
    const float* K  = (const float*)d_in[1];
    const float* V  = (const float*)d_in[2];
    const int*   mr = (const int*)d_in[3];
    const int*   mc = (const int*)d_in[4];
    const int nmask = in_sizes[3];
    float* Out = (float*)d_out;

    cudaFuncSetAttribute(attn_mma_k, cudaFuncAttributeMaxDynamicSharedMemorySize,
                         (int)SMEM_BYTES);

    prep_k<<<2048, 256>>>(Q, K, V);
    scatter_mask_k<<<(nmask + 255) / 256, 256>>>(mr, mc, nmask);
    attn_mma_k<<<(NQ / BM) * SPLITS, THREADS, SMEM_BYTES>>>();
    combine_k<<<NQ * DD / 8 / 256, 256>>>(Out);
}